// round 14
// baseline (speedup 1.0000x reference)
#include <cuda_runtime.h>
#include <cstdint>

#define B_ROWS 8192
#define C_ROWS 10000
#define D_DIM  512
#define WARPS_PER_CTA 16
#define THREADS (32 * WARPS_PER_CTA)         // 512
#define GRID_CTAS (B_ROWS / WARPS_PER_CTA)   // 512, warp-per-row

// ---------------------------------------------------------------------------
// Champion configuration: warp-per-row, 512x512t, <=32 regs (4 CTAs/SM),
// barrier-free detect head, per-warp ballot, one atomic per CTA.
// Best measured kernel dur (9.088us) + best DRAM% (39.4) of all variants.
// ---------------------------------------------------------------------------
__global__ __launch_bounds__(THREADS, 4)
void center_loss_fused(const float* __restrict__ x,
                       const void*  __restrict__ labels,
                       const float* __restrict__ centers,
                       float* __restrict__ out)
{
    __shared__ float s_part[WARPS_PER_CTA];

    const int t    = threadIdx.x;
    const int warp = t >> 5;
    const int lane = t & 31;

    const int row = blockIdx.x * WARPS_PER_CTA + warp;   // 0..8191

    // ---- head: issue everything label-independent FIRST, no barriers ----
    // dtype-detect word: first 8 u64-interpreted words (64 B, in-bounds for
    // both 8192*i32 and 8192*i64 layouts). Genuine i64 labels < 10000 keep
    // every word < 10000; a packed i32 pair exceeds 2^32 whenever the
    // odd-index label != 0 (checked over 16 labels -> certain in practice).
    unsigned long long dw = ((const unsigned long long*)labels)[lane & 7];
    // int32 interpretation: ALWAYS in-bounds, issue now (likely path).
    int l32 = ((const int*)labels)[row];

    // x row: 4 float4 per lane, label-independent, issue all now.
    const float4* __restrict__ xr =
        reinterpret_cast<const float4*>(x + (size_t)row * D_DIM);
    float4 a0 = xr[lane];
    float4 a1 = xr[lane + 32];
    float4 a2 = xr[lane + 64];
    float4 a3 = xr[lane + 96];

    // ---- resolve label (per-warp ballot; no __syncthreads) ----
    unsigned big = __ballot_sync(0xFFFFFFFFu, dw >= (unsigned long long)C_ROWS);
    long long lbl;
    if (big == 0u)  lbl = ((const long long*)labels)[row];  // true int64 (rare)
    else            lbl = (long long)l32;                    // int32 (in flight)

    const float4* __restrict__ cr =
        reinterpret_cast<const float4*>(centers + (size_t)lbl * D_DIM);

    // ---- center row + reduction ----
    float4 c0 = cr[lane];
    float4 c1 = cr[lane + 32];
    float4 c2 = cr[lane + 64];
    float4 c3 = cr[lane + 96];

    float s = 0.0f, d;
    d = a0.x - c0.x; s = fmaf(d, d, s);
    d = a0.y - c0.y; s = fmaf(d, d, s);
    d = a0.z - c0.z; s = fmaf(d, d, s);
    d = a0.w - c0.w; s = fmaf(d, d, s);
    d = a1.x - c1.x; s = fmaf(d, d, s);
    d = a1.y - c1.y; s = fmaf(d, d, s);
    d = a1.z - c1.z; s = fmaf(d, d, s);
    d = a1.w - c1.w; s = fmaf(d, d, s);
    d = a2.x - c2.x; s = fmaf(d, d, s);
    d = a2.y - c2.y; s = fmaf(d, d, s);
    d = a2.z - c2.z; s = fmaf(d, d, s);
    d = a2.w - c2.w; s = fmaf(d, d, s);
    d = a3.x - c3.x; s = fmaf(d, d, s);
    d = a3.y - c3.y; s = fmaf(d, d, s);
    d = a3.z - c3.z; s = fmaf(d, d, s);
    d = a3.w - c3.w; s = fmaf(d, d, s);

    // warp reduce -> row distance on lane 0
    #pragma unroll
    for (int off = 16; off > 0; off >>= 1)
        s += __shfl_xor_sync(0xFFFFFFFFu, s, off);

    if (lane == 0) {
        // per-row clamp, pre-scaled by 1/B
        float dist = fminf(fmaxf(s, 1e-12f), 1e12f);
        s_part[warp] = dist * (1.0f / (float)B_ROWS);
    }
    __syncthreads();

    // one atomic per CTA (512 total)
    if (t == 0) {
        float p = 0.0f;
        #pragma unroll
        for (int w = 0; w < WARPS_PER_CTA; w++) p += s_part[w];
        atomicAdd(out, p);
    }
}

// ---------------------------------------------------------------------------
// Launch. Inputs identified BY SIZE (robust to metadata ordering):
//   x: 4,194,304 f32 | labels: 8,192 (i32/i64, device-detected) |
//   centers: 5,120,000 f32. Output: scalar f32 (atomic-accumulated).
// ---------------------------------------------------------------------------
extern "C" void kernel_launch(void* const* d_in, const int* in_sizes, int n_in,
                              void* d_out, int out_size)
{
    const float* x       = nullptr;
    const void*  labels  = nullptr;
    const float* centers = nullptr;

    for (int i = 0; i < n_in; i++) {
        if (in_sizes[i] == B_ROWS * D_DIM)       x       = (const float*)d_in[i];
        else if (in_sizes[i] == B_ROWS)          labels  = d_in[i];
        else if (in_sizes[i] == C_ROWS * D_DIM)  centers = (const float*)d_in[i];
    }

    float* out = (float*)d_out;

    cudaMemsetAsync(out, 0, sizeof(float));   // zero accumulator each replay
    center_loss_fused<<<GRID_CTAS, THREADS>>>(x, labels, centers, out);
}

// round 15
// speedup vs baseline: 1.2132x; 1.2132x over previous
#include <cuda_runtime.h>
#include <cstdint>

#define B_ROWS 8192
#define C_ROWS 10000
#define D_DIM  512
#define WARPS_PER_CTA 16
#define THREADS (32 * WARPS_PER_CTA)         // 512
#define GRID_CTAS (B_ROWS / WARPS_PER_CTA)   // 512, warp-per-row

// ---------------------------------------------------------------------------
// Exact reproduction of the R10 configuration (bench-best 8.32us draw):
// warp-per-row, 512x512t, launch_bounds(512,3) [-> ~40 regs, 3 CTAs/SM],
// barrier-free detect head, per-warp ballot, one atomic per CTA.
// Discriminates "R10 config genuinely faster on bench" vs "noise draw".
// ---------------------------------------------------------------------------
__global__ __launch_bounds__(THREADS, 3)
void center_loss_fused(const float* __restrict__ x,
                       const void*  __restrict__ labels,
                       const float* __restrict__ centers,
                       float* __restrict__ out)
{
    __shared__ float s_part[WARPS_PER_CTA];

    const int t    = threadIdx.x;
    const int warp = t >> 5;
    const int lane = t & 31;

    const int row = blockIdx.x * WARPS_PER_CTA + warp;   // 0..8191

    // ---- head: issue everything label-independent FIRST, no barriers ----
    // dtype-detect word: first 8 u64-interpreted words (64 B, in-bounds for
    // both 8192*i32 and 8192*i64 layouts). Genuine i64 labels < 10000 keep
    // every word < 10000; a packed i32 pair exceeds 2^32 whenever the
    // odd-index label != 0 (checked over 16 labels -> certain in practice).
    unsigned long long dw = ((const unsigned long long*)labels)[lane & 7];
    // int32 interpretation: ALWAYS in-bounds, issue now (likely path).
    int l32 = ((const int*)labels)[row];

    // x row: 4 float4 per lane, label-independent, issue all now.
    const float4* __restrict__ xr =
        reinterpret_cast<const float4*>(x + (size_t)row * D_DIM);
    float4 a0 = xr[lane];
    float4 a1 = xr[lane + 32];
    float4 a2 = xr[lane + 64];
    float4 a3 = xr[lane + 96];

    // ---- resolve label (per-warp ballot; no __syncthreads) ----
    unsigned big = __ballot_sync(0xFFFFFFFFu, dw >= (unsigned long long)C_ROWS);
    long long lbl;
    if (big == 0u)  lbl = ((const long long*)labels)[row];  // true int64 (rare)
    else            lbl = (long long)l32;                    // int32 (in flight)

    const float4* __restrict__ cr =
        reinterpret_cast<const float4*>(centers + (size_t)lbl * D_DIM);

    // ---- center row + reduction ----
    float4 c0 = cr[lane];
    float4 c1 = cr[lane + 32];
    float4 c2 = cr[lane + 64];
    float4 c3 = cr[lane + 96];

    float s = 0.0f, d;
    d = a0.x - c0.x; s = fmaf(d, d, s);
    d = a0.y - c0.y; s = fmaf(d, d, s);
    d = a0.z - c0.z; s = fmaf(d, d, s);
    d = a0.w - c0.w; s = fmaf(d, d, s);
    d = a1.x - c1.x; s = fmaf(d, d, s);
    d = a1.y - c1.y; s = fmaf(d, d, s);
    d = a1.z - c1.z; s = fmaf(d, d, s);
    d = a1.w - c1.w; s = fmaf(d, d, s);
    d = a2.x - c2.x; s = fmaf(d, d, s);
    d = a2.y - c2.y; s = fmaf(d, d, s);
    d = a2.z - c2.z; s = fmaf(d, d, s);
    d = a2.w - c2.w; s = fmaf(d, d, s);
    d = a3.x - c3.x; s = fmaf(d, d, s);
    d = a3.y - c3.y; s = fmaf(d, d, s);
    d = a3.z - c3.z; s = fmaf(d, d, s);
    d = a3.w - c3.w; s = fmaf(d, d, s);

    // warp reduce -> row distance on lane 0
    #pragma unroll
    for (int off = 16; off > 0; off >>= 1)
        s += __shfl_xor_sync(0xFFFFFFFFu, s, off);

    if (lane == 0) {
        // per-row clamp, pre-scaled by 1/B
        float dist = fminf(fmaxf(s, 1e-12f), 1e12f);
        s_part[warp] = dist * (1.0f / (float)B_ROWS);
    }
    __syncthreads();

    // one atomic per CTA (512 total)
    if (t == 0) {
        float p = 0.0f;
        #pragma unroll
        for (int w = 0; w < WARPS_PER_CTA; w++) p += s_part[w];
        atomicAdd(out, p);
    }
}

// ---------------------------------------------------------------------------
// Launch. Inputs identified BY SIZE (robust to metadata ordering):
//   x: 4,194,304 f32 | labels: 8,192 (i32/i64, device-detected) |
//   centers: 5,120,000 f32. Output: scalar f32 (atomic-accumulated).
// ---------------------------------------------------------------------------
extern "C" void kernel_launch(void* const* d_in, const int* in_sizes, int n_in,
                              void* d_out, int out_size)
{
    const float* x       = nullptr;
    const void*  labels  = nullptr;
    const float* centers = nullptr;

    for (int i = 0; i < n_in; i++) {
        if (in_sizes[i] == B_ROWS * D_DIM)       x       = (const float*)d_in[i];
        else if (in_sizes[i] == B_ROWS)          labels  = d_in[i];
        else if (in_sizes[i] == C_ROWS * D_DIM)  centers = (const float*)d_in[i];
    }

    float* out = (float*)d_out;

    cudaMemsetAsync(out, 0, sizeof(float));   // zero accumulator each replay
    center_loss_fused<<<GRID_CTAS, THREADS>>>(x, labels, centers, out);
}